// round 2
// baseline (speedup 1.0000x reference)
#include <cuda_runtime.h>
#include <math.h>

#define NN 100000
#define EE 1600000
#define FF 512
#define HH 256

// ---------------- scratch (static device globals; no allocation) ------------
__device__ float g_B0[(size_t)NN * HH];
__device__ float g_B1[(size_t)NN * HH];
__device__ float g_B2[(size_t)NN * HH];
__device__ int   g_odeg[NN];
__device__ int   g_ideg[NN];
__device__ float g_nsrc[NN];
__device__ float g_ndst[NN];
__device__ float g_psum[HH];
__device__ float g_pmax[HH];

// ---------------- helpers ---------------------------------------------------
__device__ __forceinline__ void atomicMaxFloat(float* addr, float v) {
    // Standard sign-split trick: works for mixed-sign floats.
    if (v >= 0.0f) atomicMax((int*)addr, __float_as_int(v));
    else           atomicMin((unsigned int*)addr, __float_as_uint(v));
}

__device__ __forceinline__ float leaky(float x) {
    return x > 0.0f ? x : 0.01f * x;
}

// ---------------- kernels ---------------------------------------------------
__global__ void k_zero(float4* p, int n4) {
    int i = blockIdx.x * blockDim.x + threadIdx.x;
    if (i < n4) p[i] = make_float4(0.f, 0.f, 0.f, 0.f);
}

__global__ void k_degree(const int* __restrict__ src, const int* __restrict__ dst) {
    int e = blockIdx.x * blockDim.x + threadIdx.x;
    if (e < EE) {
        atomicAdd(&g_odeg[src[e]], 1);
        atomicAdd(&g_ideg[dst[e]], 1);
    }
}

__global__ void k_norm() {
    int i = blockIdx.x * blockDim.x + threadIdx.x;
    if (i < NN) {
        g_nsrc[i] = rsqrtf(fmaxf((float)g_odeg[i], 1.0f));
        g_ndst[i] = rsqrtf(fmaxf((float)g_ideg[i], 1.0f));
    }
    if (blockIdx.x == 0 && threadIdx.x < HH) {
        g_psum[threadIdx.x] = 0.0f;
        g_pmax[threadIdx.x] = -INFINITY;
    }
}

// C[N,256] = (A[N,K] * norm[row]) @ W[K,256].  BM=64, BN=256, BK=32, 256 thr,
// each thread computes an 8x8 micro-tile.
template <int K>
__global__ void __launch_bounds__(256)
k_gemm(const float* __restrict__ A, const float* __restrict__ W,
       const float* __restrict__ norm, float* __restrict__ C) {
    __shared__ float As[32][64];    // [k][m] (transposed)
    __shared__ float Bs[32][256];   // [k][n]
    const int tid = threadIdx.x;
    const int m0  = blockIdx.x * 64;
    const int tr  = tid >> 5;   // 0..7  (row group)
    const int tc  = tid & 31;   // 0..31 (col group)

    float acc[8][8] = {};

    for (int k0 = 0; k0 < K; k0 += 32) {
        // A tile: 64 rows x 32 k-cols, scaled by norm[row]
        #pragma unroll
        for (int i = 0; i < 2; i++) {
            int idx = tid + i * 256;          // 0..511
            int r   = idx >> 3;               // 0..63
            int c   = (idx & 7) << 2;         // 0..28 step 4
            int grow = m0 + r;
            float4 v = make_float4(0.f, 0.f, 0.f, 0.f);
            float  nv = 0.f;
            if (grow < NN) {
                v  = *(const float4*)(A + (size_t)grow * K + k0 + c);
                nv = norm[grow];
            }
            As[c + 0][r] = v.x * nv;
            As[c + 1][r] = v.y * nv;
            As[c + 2][r] = v.z * nv;
            As[c + 3][r] = v.w * nv;
        }
        // B tile: 32 k-rows x 256 cols
        #pragma unroll
        for (int i = 0; i < 8; i++) {
            int idx = tid + i * 256;          // 0..2047
            int r   = idx >> 6;               // 0..31
            int c   = (idx & 63) << 2;        // 0..252 step 4
            *(float4*)&Bs[r][c] = *(const float4*)(W + (size_t)(k0 + r) * HH + c);
        }
        __syncthreads();

        #pragma unroll
        for (int k = 0; k < 32; k++) {
            float a[8], b[8];
            #pragma unroll
            for (int i = 0; i < 8; i++) a[i] = As[k][tr * 8 + i];
            #pragma unroll
            for (int j = 0; j < 8; j++) b[j] = Bs[k][tc * 8 + j];
            #pragma unroll
            for (int i = 0; i < 8; i++)
                #pragma unroll
                for (int j = 0; j < 8; j++)
                    acc[i][j] = fmaf(a[i], b[j], acc[i][j]);
        }
        __syncthreads();
    }

    #pragma unroll
    for (int i = 0; i < 8; i++) {
        int grow = m0 + tr * 8 + i;
        if (grow < NN) {
            #pragma unroll
            for (int j = 0; j < 8; j += 4) {
                float4 v = make_float4(acc[i][j], acc[i][j + 1], acc[i][j + 2], acc[i][j + 3]);
                *(float4*)(C + (size_t)grow * HH + tc * 8 + j) = v;
            }
        }
    }
}

// A[dst[e]] += X[src[e]]  (rows of 256 floats).  One warp per edge, float4 REDs.
__global__ void k_scatter(const float4* __restrict__ X, float4* __restrict__ A,
                          const int* __restrict__ src, const int* __restrict__ dst) {
    int w    = (blockIdx.x * blockDim.x + threadIdx.x) >> 5;
    int lane = threadIdx.x & 31;
    if (w >= EE) return;
    int s = __ldg(src + w);
    int d = __ldg(dst + w);
    const float4* xs = X + (size_t)s * (HH / 4);
    float4*       ad = A + (size_t)d * (HH / 4);
    float4 v0 = xs[lane];
    float4 v1 = xs[lane + 32];
    atomicAdd(ad + lane, v0);        // sm_90+ vector RED (4x fewer atomics)
    atomicAdd(ad + lane + 32, v1);
}

// O = leaky(A * ndst[row] + b[col]), elementwise over [N,256]
__global__ void k_act(const float4* __restrict__ A, const float* __restrict__ ndst,
                      const float* __restrict__ b, float4* __restrict__ O) {
    int i = blockIdx.x * blockDim.x + threadIdx.x;    // over N*64 float4s
    if (i >= NN * (HH / 4)) return;
    int row = i >> 6;
    int c4  = (i & 63) << 2;
    float  nd = ndst[row];
    float4 v  = A[i];
    float4 bb = *(const float4*)(b + c4);
    v.x = leaky(fmaf(v.x, nd, bb.x));
    v.y = leaky(fmaf(v.y, nd, bb.y));
    v.z = leaky(fmaf(v.z, nd, bb.z));
    v.w = leaky(fmaf(v.w, nd, bb.w));
    O[i] = v;
}

// Column-wise sum + max of h2 = leaky(B * ndst + b2), h2 materialized on the fly.
__global__ void k_pool(const float* __restrict__ B, const float* __restrict__ ndst,
                       const float* __restrict__ b2) {
    int col = threadIdx.x;              // 256 threads = 256 dims
    int n0  = blockIdx.x * 256;
    float bb = b2[col];
    float s = 0.0f, m = -INFINITY;
    int nend = min(n0 + 256, NN);
    for (int r = n0; r < nend; r++) {
        float v = leaky(fmaf(B[(size_t)r * HH + col], ndst[r], bb));
        s += v;
        m = fmaxf(m, v);
    }
    atomicAdd(&g_psum[col], s);
    atomicMaxFloat(&g_pmax[col], m);
}

// Generator head: pooled(768) @ Wg(768x1024) + bg -> mu/sigma/feat_new/log_prob
__global__ void k_final(const float* __restrict__ B, const int* __restrict__ node_index,
                        const float* __restrict__ b2,
                        const float* __restrict__ Wg, const float* __restrict__ bg,
                        const float* __restrict__ eps, float* __restrict__ out) {
    __shared__ float pooled[768];
    __shared__ float red[256];
    int t  = threadIdx.x;               // 256 threads
    int ni = *node_index;

    pooled[t]       = g_psum[t];
    pooled[256 + t] = g_pmax[t];
    float nd = g_ndst[ni];
    pooled[512 + t] = leaky(fmaf(B[(size_t)ni * HH + t], nd, b2[t]));
    __syncthreads();

    float fdv[4];
    #pragma unroll
    for (int o = 0; o < 4; o++) {
        int k = t + o * 256;
        float acc = bg[k];
        for (int i = 0; i < 768; i++)
            acc = fmaf(pooled[i], Wg[(size_t)i * 1024 + k], acc);
        fdv[o] = acc;
    }
    // thread t owns mu[t], mu[t+256], sigma[t], sigma[t+256]
    float mu1 = fdv[0],        mu2 = fdv[1];
    float sg1 = fabsf(fdv[2]), sg2 = fabsf(fdv[3]);
    float e1 = eps[t], e2 = eps[t + 256];
    float fn1 = fmaf(sg1, e1, mu1);
    float fn2 = fmaf(sg2, e2, mu2);

    out[t]              = fn1;  out[t + 256]        = fn2;   // feat_new
    out[512 + t]        = mu1;  out[512 + t + 256]  = mu2;   // mu
    out[1024 + t]       = sg1;  out[1024 + t + 256] = sg2;   // sigma

    const float HALF_LOG_2PI = 0.9189385332046727f;
    float r1 = (fn1 - mu1) / sg1;
    float r2 = (fn2 - mu2) / sg2;
    float lp = (-0.5f * r1 * r1 - logf(sg1) - HALF_LOG_2PI)
             + (-0.5f * r2 * r2 - logf(sg2) - HALF_LOG_2PI);
    red[t] = lp;
    __syncthreads();
    for (int off = 128; off > 0; off >>= 1) {
        if (t < off) red[t] += red[t + off];
        __syncthreads();
    }
    if (t == 0) out[1536] = red[0] / 512.0f;
}

// ---------------- launcher ---------------------------------------------------
extern "C" void kernel_launch(void* const* d_in, const int* in_sizes, int n_in,
                              void* d_out, int out_size) {
    const float* feat = (const float*)d_in[0];
    const int*   src  = (const int*)d_in[1];
    const int*   dst  = (const int*)d_in[2];
    const int*   nidx = (const int*)d_in[3];
    const float* W1   = (const float*)d_in[4];
    const float* b1   = (const float*)d_in[5];
    const float* W2   = (const float*)d_in[6];
    const float* b2   = (const float*)d_in[7];
    const float* Wg   = (const float*)d_in[8];
    const float* bg   = (const float*)d_in[9];
    const float* eps  = (const float*)d_in[10];
    float* out = (float*)d_out;

    void *p0, *p1, *p2, *pod, *pid, *pns, *pnd;
    cudaGetSymbolAddress(&p0, g_B0);
    cudaGetSymbolAddress(&p1, g_B1);
    cudaGetSymbolAddress(&p2, g_B2);
    cudaGetSymbolAddress(&pod, g_odeg);
    cudaGetSymbolAddress(&pid, g_ideg);
    cudaGetSymbolAddress(&pns, g_nsrc);
    cudaGetSymbolAddress(&pnd, g_ndst);
    float* B0 = (float*)p0;
    float* B1 = (float*)p1;
    float* B2 = (float*)p2;
    float* nsrc = (float*)pns;
    float* ndst = (float*)pnd;

    const int NH4      = NN * (HH / 4);   // 6,400,000 float4s
    const int Z_BLKS   = NH4 / 256;       // 25000
    const int DEG_BLKS = (EE + 255) / 256;
    const int N_BLKS   = (NN + 255) / 256;
    const int GEMM_BLKS = (NN + 63) / 64; // 1563
    const int SCAT_BLKS = EE / 8;         // 200000 (8 edges/block, warp per edge)

    // degrees + norms
    k_zero<<<(NN / 4 + 255) / 256, 256>>>((float4*)pod, NN / 4);
    k_zero<<<(NN / 4 + 255) / 256, 256>>>((float4*)pid, NN / 4);
    k_degree<<<DEG_BLKS, 256>>>(src, dst);
    k_norm<<<N_BLKS, 256>>>();

    // layer 1: B0 = (feat*nsrc)@W1 ; B1 = scatter(B0) ; B0 = leaky(B1*ndst+b1)
    k_gemm<FF><<<GEMM_BLKS, 256>>>(feat, W1, nsrc, B0);
    k_zero<<<Z_BLKS, 256>>>((float4*)B1, NH4);
    k_scatter<<<SCAT_BLKS, 256>>>((const float4*)B0, (float4*)B1, src, dst);
    k_act<<<Z_BLKS, 256>>>((const float4*)B1, ndst, b1, (float4*)B0);

    // layer 2: B2 = (B0*nsrc)@W2 ; B0 = scatter(B2)  (h2 applied on the fly later)
    k_gemm<HH><<<GEMM_BLKS, 256>>>(B0, W2, nsrc, B2);
    k_zero<<<Z_BLKS, 256>>>((float4*)B0, NH4);
    k_scatter<<<SCAT_BLKS, 256>>>((const float4*)B2, (float4*)B0, src, dst);

    // pooling + head
    k_pool<<<N_BLKS, 256>>>(B0, ndst, b2);
    k_final<<<1, 256>>>(B0, nidx, b2, Wg, bg, eps, out);
}